// round 2
// baseline (speedup 1.0000x reference)
#include <cuda_runtime.h>
#include <cstdint>

// ---------------- problem constants ----------------
constexpr int BB = 16;
constexpr int N0 = 8192;
constexpr int P1 = 512;
constexpr int P2 = 128;
constexpr int KNN = 16;
constexpr int C1 = 128;   // SA1 out channels
constexpr int C2 = 256;   // SA2 out channels

// ---------------- scratch arena (device globals; no allocation) ----------------
// xyz buffers planar (B,3,P); feature buffers point-major (B,P,C) for coalesced
// SA writes and contiguous gather reads.
constexpr int OFF_L1XYZ = 0;                              // (B,3,P1)
constexpr int OFF_L1PTS = OFF_L1XYZ + BB * 3 * P1;        // (B,P1,C1)
constexpr int OFF_L2XYZ = OFF_L1PTS + BB * P1 * C1;       // (B,3,P2)
constexpr int OFF_L2PTS = OFF_L2XYZ + BB * 3 * P2;        // (B,P2,C2)
constexpr int OFF_W1AT  = OFF_L2PTS + BB * P2 * C2;       // (8,64)   rows 6,7 zero
constexpr int OFF_W1BT  = OFF_W1AT + 8 * 64;              // (64,128)
constexpr int OFF_W2AT  = OFF_W1BT + 64 * 128;            // (132,128) row 131 zero
constexpr int OFF_W2BT  = OFF_W2AT + 132 * 128;           // (128,256)
constexpr int OFF_W3AT  = OFF_W2BT + 128 * 256;           // (260,512) row 259 zero
constexpr int OFF_W3BT  = OFF_W3AT + 260 * 512;           // (512,256)
constexpr int F_TOTAL   = OFF_W3BT + 512 * 256;

constexpr int OFF_FPS1 = 0;
constexpr int OFF_KNN1 = OFF_FPS1 + BB * P1;
constexpr int OFF_FPS2 = OFF_KNN1 + BB * P1 * KNN;
constexpr int OFF_KNN2 = OFF_FPS2 + BB * P2;
constexpr int I_TOTAL  = OFF_KNN2 + BB * P2 * KNN;

__device__ float g_f[F_TOTAL];
__device__ int   g_i[I_TOTAL];

// ---------------- merged weight transpose + pad: W(O,I) -> WT(Ipad,O) ----------------
__global__ void prep_weights(const float* __restrict__ W1a, const float* __restrict__ W1b,
                             const float* __restrict__ W2a, const float* __restrict__ W2b,
                             const float* __restrict__ W3a, const float* __restrict__ W3b) {
    int idx = blockIdx.x * blockDim.x + threadIdx.x;
    if (idx < 512) {                      // W1A: (64,6) -> (8,64), pad rows 6,7
        int i = idx >> 6, o = idx & 63;
        g_f[OFF_W1AT + idx] = (i < 6) ? W1a[o * 6 + i] : 0.f; return;
    }
    idx -= 512;
    if (idx < 8192) {                     // W1B: (128,64) -> (64,128)
        int i = idx >> 7, o = idx & 127;
        g_f[OFF_W1BT + idx] = W1b[o * 64 + i]; return;
    }
    idx -= 8192;
    if (idx < 16896) {                    // W2A: (128,131) -> (132,128), pad row 131
        int i = idx >> 7, o = idx & 127;
        g_f[OFF_W2AT + idx] = (i < 131) ? W2a[o * 131 + i] : 0.f; return;
    }
    idx -= 16896;
    if (idx < 32768) {                    // W2B: (256,128) -> (128,256)
        int i = idx >> 8, o = idx & 255;
        g_f[OFF_W2BT + idx] = W2b[o * 128 + i]; return;
    }
    idx -= 32768;
    if (idx < 133120) {                   // W3A: (512,259) -> (260,512), pad row 259
        int i = idx >> 9, o = idx & 511;
        g_f[OFF_W3AT + idx] = (i < 259) ? W3a[o * 259 + i] : 0.f; return;
    }
    idx -= 133120;
    if (idx < 131072) {                   // W3B: (256,512) -> (512,256)
        int i = idx >> 8, o = idx & 255;
        g_f[OFF_W3BT + idx] = W3b[o * 512 + i]; return;
    }
}

// ---------------- farthest point sampling ----------------
// One block per batch. Coords + running min-dist in registers. Distance uses
// explicit non-contracted subtract-then-square to mirror the reference
// lowering; argmax tie-break = lowest index (jnp.argmax semantics).
template <int N, int NPOINT, int THREADS, int XYZ_OFF, int IDX_OFF>
__global__ void __launch_bounds__(THREADS) fps_kernel(const float* __restrict__ xyz_in) {
    constexpr int PPT = (N + THREADS - 1) / THREADS;
    const float* xyz;
    if constexpr (XYZ_OFF >= 0) xyz = g_f + XYZ_OFF; else xyz = xyz_in;

    int b = blockIdx.x, t = threadIdx.x;
    const float* xb = xyz + (size_t)b * 3 * N;

    float px[PPT], py[PPT], pz[PPT], dd[PPT];
#pragma unroll
    for (int i = 0; i < PPT; i++) {
        int p = t + i * THREADS;
        bool ok = (p < N);
        px[i] = ok ? xb[p] : 0.f;
        py[i] = ok ? xb[N + p] : 0.f;
        pz[i] = ok ? xb[2 * N + p] : 0.f;
        dd[i] = ok ? 1e10f : -1e30f;   // excluded slots never win argmax
    }

    __shared__ float sv[THREADS / 32];
    __shared__ int   si[THREADS / 32];
    __shared__ int   sfar;

    int far = 0;
    int* ob = g_i + IDX_OFF + b * NPOINT;

    for (int j = 0; j < NPOINT; j++) {
        if (t == 0) ob[j] = far;
        float cx = __ldg(xb + far);
        float cy = __ldg(xb + N + far);
        float cz = __ldg(xb + 2 * N + far);

        float best = -1e30f; int bidx = 0x7fffffff;
#pragma unroll
        for (int i = 0; i < PPT; i++) {
            float dx = __fsub_rn(px[i], cx);
            float dy = __fsub_rn(py[i], cy);
            float dz = __fsub_rn(pz[i], cz);
            float d  = __fadd_rn(__fadd_rn(__fmul_rn(dx, dx), __fmul_rn(dy, dy)),
                                 __fmul_rn(dz, dz));
            float nd = fminf(dd[i], d);
            dd[i] = nd;
            if (nd > best) { best = nd; bidx = t + i * THREADS; }  // ascending: > keeps lowest idx
        }
#pragma unroll
        for (int off = 16; off; off >>= 1) {
            float ov = __shfl_down_sync(0xffffffffu, best, off);
            int   oi = __shfl_down_sync(0xffffffffu, bidx, off);
            if (ov > best || (ov == best && oi < bidx)) { best = ov; bidx = oi; }
        }
        if ((t & 31) == 0) { sv[t >> 5] = best; si[t >> 5] = bidx; }
        __syncthreads();
        if (t < 32) {
            constexpr int NW = THREADS / 32;
            float v = (t < NW) ? sv[t] : -1e30f;
            int  ix = (t < NW) ? si[t] : 0x7fffffff;
#pragma unroll
            for (int off = 16; off; off >>= 1) {
                float ov = __shfl_down_sync(0xffffffffu, v, off);
                int   oi = __shfl_down_sync(0xffffffffu, ix, off);
                if (ov > v || (ov == v && oi < ix)) { v = ov; ix = oi; }
            }
            if (t == 0) sfar = ix;
        }
        __syncthreads();
        far = sfar;
    }
}

// ---------------- gather sampled xyz (planar -> planar) ----------------
template <int NSRC, int PDST, int SRC_OFF, int IDX_OFF, int DST_OFF>
__global__ void gather_kernel(const float* __restrict__ src_in) {
    const float* src;
    if constexpr (SRC_OFF >= 0) src = g_f + SRC_OFF; else src = src_in;
    int b = blockIdx.x;
    for (int p = threadIdx.x; p < PDST; p += blockDim.x) {
        int j = g_i[IDX_OFF + b * PDST + p];
#pragma unroll
        for (int c = 0; c < 3; c++)
            g_f[DST_OFF + (b * 3 + c) * PDST + p] = src[((size_t)b * 3 + c) * NSRC + j];
    }
}

// ---------------- kNN: smem-tiled points, warp-distributed sorted top-16 ----------------
// Lanes 0..15 each hold one packed (monotonic-dist-bits<<32 | idx) key of the
// current 16 smallest (ascending). Float threshold pre-filter + ballot-gated
// shfl_up insertion -> O(accepted) insertion cost.
__device__ __forceinline__ unsigned long long pack_key(float d, int i) {
    unsigned b = __float_as_uint(d);
    b = (b & 0x80000000u) ? ~b : (b | 0x80000000u);   // total order over floats
    return ((unsigned long long)b << 32) | (unsigned)i;
}

template <int P, int N, int TILE, int CENT_OFF, int PTS_OFF, int OUT_OFF>
__global__ void __launch_bounds__(256) knn_kernel(const float* __restrict__ pts_in) {
    __shared__ float sx[TILE], sy[TILE], sz[TILE];
    const float* cent = g_f + CENT_OFF;
    const float* pts;
    if constexpr (PTS_OFF >= 0) pts = g_f + PTS_OFF; else pts = pts_in;

    int b = blockIdx.x / (P / 8);                       // 8 warps = 8 centroids, same batch
    int p = (blockIdx.x % (P / 8)) * 8 + (threadIdx.x >> 5);
    int lane = threadIdx.x & 31;

    const float* cb = cent + b * 3 * P;
    const float* pb = pts + (size_t)b * 3 * N;
    float cx = cb[p], cy = cb[P + p], cz = cb[2 * P + p];
    float c2 = cx * cx + cy * cy + cz * cz;

    unsigned long long mykey = 0xFF800000FFFFFFFFull;   // pack(+inf, ~0)
    float thrf = __int_as_float(0x7f800000);            // +inf

    for (int t0 = 0; t0 < N; t0 += TILE) {
        __syncthreads();
        for (int i = threadIdx.x; i < TILE; i += 256) {
            sx[i] = pb[t0 + i];
            sy[i] = pb[N + t0 + i];
            sz[i] = pb[2 * N + t0 + i];
        }
        __syncthreads();
        for (int c0 = 0; c0 < TILE; c0 += 32) {
            int ii = c0 + lane;
            float x = sx[ii], y = sy[ii], z = sz[ii];
            float d = c2 - 2.f * (cx * x + cy * y + cz * z) + (x * x + y * y + z * z);
            unsigned m = __ballot_sync(0xffffffffu, d <= thrf);
            if (m) {
                unsigned long long key = pack_key(d, t0 + ii);
                while (m) {
                    int src = __ffs(m) - 1;
                    m &= m - 1;
                    unsigned long long K = __shfl_sync(0xffffffffu, key, src);
                    unsigned long long thr = __shfl_sync(0xffffffffu, mykey, 15);
                    unsigned long long up = __shfl_up_sync(0xffffffffu, mykey, 1);
                    if (K < thr && lane < 16 && mykey > K)
                        mykey = (lane > 0 && up > K) ? up : K;
                }
                unsigned long long k15 = __shfl_sync(0xffffffffu, mykey, 15);
                unsigned hb = (unsigned)(k15 >> 32);
                unsigned ob = (hb & 0x80000000u) ? (hb & 0x7fffffffu) : ~hb;
                thrf = __uint_as_float(ob);
            }
        }
    }
    if (lane < 16)
        g_i[OUT_OFF + ((b * P + p) << 4) + lane] = (int)(mykey & 0xffffffffu);
}

// ---------------- SA1: group + MLP(6->64 relu ->128) + maxpool over K=16 ----------------
// i-major smem layouts: feat[n][8], hid[n][64]; float4 broadcast loads ->
// FFMA-bound inner loops. One centroid per block; weights stay hot in L1.
__global__ void __launch_bounds__(128) sa1_kernel(const float* __restrict__ xyz,
                                                  const float* __restrict__ b1a,
                                                  const float* __restrict__ b1b) {
    __shared__ float feat[16 * 8];
    __shared__ float hid[16 * 64];
    int t = threadIdx.x;
    int cid = blockIdx.x;
    int b = cid >> 9, p = cid & 511;

    if (t < 16) {
        int j = g_i[OFF_KNN1 + (cid << 4) + t];
        const float* xb = xyz + (size_t)b * 3 * N0;
        float vx = xb[j], vy = xb[N0 + j], vz = xb[2 * N0 + j];
        const float* cxb = g_f + OFF_L1XYZ + b * 3 * P1;
        feat[t * 8 + 0] = vx - cxb[p];
        feat[t * 8 + 1] = vy - cxb[P1 + p];
        feat[t * 8 + 2] = vz - cxb[2 * P1 + p];
        feat[t * 8 + 3] = vx;
        feat[t * 8 + 4] = vy;
        feat[t * 8 + 5] = vz;
        feat[t * 8 + 6] = 0.f;
        feat[t * 8 + 7] = 0.f;
    }
    __syncthreads();

    if (t < 64) {
        float acc[16];
#pragma unroll
        for (int n = 0; n < 16; n++) acc[n] = 0.f;
#pragma unroll
        for (int i4 = 0; i4 < 2; i4++) {
            float w0 = g_f[OFF_W1AT + (4 * i4 + 0) * 64 + t];
            float w1 = g_f[OFF_W1AT + (4 * i4 + 1) * 64 + t];
            float w2 = g_f[OFF_W1AT + (4 * i4 + 2) * 64 + t];
            float w3 = g_f[OFF_W1AT + (4 * i4 + 3) * 64 + t];
#pragma unroll
            for (int n = 0; n < 16; n++) {
                float4 f = *reinterpret_cast<float4*>(&feat[n * 8 + 4 * i4]);
                acc[n] += w0 * f.x + w1 * f.y + w2 * f.z + w3 * f.w;
            }
        }
        float bb = b1a[t];
#pragma unroll
        for (int n = 0; n < 16; n++) hid[n * 64 + t] = fmaxf(acc[n] + bb, 0.f);
    }
    __syncthreads();

    {
        float acc[16];
#pragma unroll
        for (int n = 0; n < 16; n++) acc[n] = 0.f;
#pragma unroll 4
        for (int h4 = 0; h4 < 16; h4++) {
            float w0 = g_f[OFF_W1BT + (4 * h4 + 0) * 128 + t];
            float w1 = g_f[OFF_W1BT + (4 * h4 + 1) * 128 + t];
            float w2 = g_f[OFF_W1BT + (4 * h4 + 2) * 128 + t];
            float w3 = g_f[OFF_W1BT + (4 * h4 + 3) * 128 + t];
#pragma unroll
            for (int n = 0; n < 16; n++) {
                float4 h = *reinterpret_cast<float4*>(&hid[n * 64 + 4 * h4]);
                acc[n] += w0 * h.x + w1 * h.y + w2 * h.z + w3 * h.w;
            }
        }
        float mx = acc[0];
#pragma unroll
        for (int n = 1; n < 16; n++) mx = fmaxf(mx, acc[n]);
        g_f[OFF_L1PTS + ((size_t)(b * P1 + p)) * C1 + t] = mx + b1b[t];   // coalesced
    }
}

// ---------------- SA2: group + MLP(131->128 relu ->256) + maxpool ----------------
__global__ void __launch_bounds__(128) sa2_kernel(const float* __restrict__ b2a,
                                                  const float* __restrict__ b2b) {
    __shared__ float feat[16 * 132];
    __shared__ float hid[16 * 128];
    __shared__ int   sj[16];
    int t = threadIdx.x;
    int cid = blockIdx.x;
    int b = cid >> 7, p = cid & 127;

    if (t < 16) sj[t] = g_i[OFF_KNN2 + (cid << 4) + t];
    __syncthreads();

    for (int idx = t; idx < 16 * 132; idx += 128) {
        int n = idx / 132, c = idx - n * 132;
        int j = sj[n];
        float v;
        if (c < 3)
            v = g_f[OFF_L1XYZ + (b * 3 + c) * P1 + j] - g_f[OFF_L2XYZ + (b * 3 + c) * P2 + p];
        else if (c < 131)
            v = g_f[OFF_L1PTS + ((size_t)(b * P1 + j)) * C1 + (c - 3)];
        else
            v = 0.f;
        feat[idx] = v;
    }
    __syncthreads();

    {
        float acc[16];
#pragma unroll
        for (int n = 0; n < 16; n++) acc[n] = 0.f;
#pragma unroll 3
        for (int i4 = 0; i4 < 33; i4++) {
            float w0 = g_f[OFF_W2AT + (4 * i4 + 0) * 128 + t];
            float w1 = g_f[OFF_W2AT + (4 * i4 + 1) * 128 + t];
            float w2 = g_f[OFF_W2AT + (4 * i4 + 2) * 128 + t];
            float w3 = g_f[OFF_W2AT + (4 * i4 + 3) * 128 + t];
#pragma unroll
            for (int n = 0; n < 16; n++) {
                float4 f = *reinterpret_cast<float4*>(&feat[n * 132 + 4 * i4]);
                acc[n] += w0 * f.x + w1 * f.y + w2 * f.z + w3 * f.w;
            }
        }
        float bb = b2a[t];
#pragma unroll
        for (int n = 0; n < 16; n++) hid[n * 128 + t] = fmaxf(acc[n] + bb, 0.f);
    }
    __syncthreads();

#pragma unroll
    for (int cc = 0; cc < 2; cc++) {
        int o = t + cc * 128;
        float acc[16];
#pragma unroll
        for (int n = 0; n < 16; n++) acc[n] = 0.f;
#pragma unroll 4
        for (int h4 = 0; h4 < 32; h4++) {
            float w0 = g_f[OFF_W2BT + (4 * h4 + 0) * 256 + o];
            float w1 = g_f[OFF_W2BT + (4 * h4 + 1) * 256 + o];
            float w2 = g_f[OFF_W2BT + (4 * h4 + 2) * 256 + o];
            float w3 = g_f[OFF_W2BT + (4 * h4 + 3) * 256 + o];
#pragma unroll
            for (int n = 0; n < 16; n++) {
                float4 h = *reinterpret_cast<float4*>(&hid[n * 128 + 4 * h4]);
                acc[n] += w0 * h.x + w1 * h.y + w2 * h.z + w3 * h.w;
            }
        }
        float mx = acc[0];
#pragma unroll
        for (int n = 1; n < 16; n++) mx = fmaxf(mx, acc[n]);
        g_f[OFF_L2PTS + ((size_t)(b * P2 + p)) * C2 + o] = mx + b2b[o];   // coalesced
    }
}

// ---------------- SA3: group-all MLP(259->512 relu ->256) + global max ----------------
__device__ __forceinline__ void atomicMaxFloat(float* addr, float v) {
    if (v >= 0.f) atomicMax((int*)addr, __float_as_int(v));
    else          atomicMin((unsigned*)addr, __float_as_uint(v));
}

__global__ void init_out_kernel(float* out, int n) {
    int i = blockIdx.x * blockDim.x + threadIdx.x;
    if (i < n) out[i] = __int_as_float(0xff800000);   // -inf
}

__global__ void __launch_bounds__(256) sa3_kernel(const float* __restrict__ b3a,
                                                  const float* __restrict__ b3b,
                                                  float* __restrict__ out) {
    __shared__ float feat[8 * 260];
    __shared__ float hid[8 * 512];
    int t = threadIdx.x;
    int b = blockIdx.x >> 4, tile = blockIdx.x & 15;   // 16 tiles of 8 points each

    for (int idx = t; idx < 8 * 260; idx += 256) {
        int n = idx / 260, c = idx - n * 260;
        int pt = tile * 8 + n;
        float v;
        if (c < 3)       v = g_f[OFF_L2XYZ + (b * 3 + c) * P2 + pt];
        else if (c < 259) v = g_f[OFF_L2PTS + ((size_t)(b * P2 + pt)) * C2 + (c - 3)];
        else             v = 0.f;
        feat[idx] = v;
    }
    __syncthreads();

#pragma unroll
    for (int cc = 0; cc < 2; cc++) {
        int h = t + cc * 256;
        float acc[8];
#pragma unroll
        for (int n = 0; n < 8; n++) acc[n] = 0.f;
#pragma unroll 5
        for (int i4 = 0; i4 < 65; i4++) {
            float w0 = g_f[OFF_W3AT + (4 * i4 + 0) * 512 + h];
            float w1 = g_f[OFF_W3AT + (4 * i4 + 1) * 512 + h];
            float w2 = g_f[OFF_W3AT + (4 * i4 + 2) * 512 + h];
            float w3 = g_f[OFF_W3AT + (4 * i4 + 3) * 512 + h];
#pragma unroll
            for (int n = 0; n < 8; n++) {
                float4 f = *reinterpret_cast<float4*>(&feat[n * 260 + 4 * i4]);
                acc[n] += w0 * f.x + w1 * f.y + w2 * f.z + w3 * f.w;
            }
        }
        float bb = b3a[h];
#pragma unroll
        for (int n = 0; n < 8; n++) hid[n * 512 + h] = fmaxf(acc[n] + bb, 0.f);
    }
    __syncthreads();

    {
        float acc[8];
#pragma unroll
        for (int n = 0; n < 8; n++) acc[n] = 0.f;
#pragma unroll 4
        for (int h4 = 0; h4 < 128; h4++) {
            float w0 = g_f[OFF_W3BT + (4 * h4 + 0) * 256 + t];
            float w1 = g_f[OFF_W3BT + (4 * h4 + 1) * 256 + t];
            float w2 = g_f[OFF_W3BT + (4 * h4 + 2) * 256 + t];
            float w3 = g_f[OFF_W3BT + (4 * h4 + 3) * 256 + t];
#pragma unroll
            for (int n = 0; n < 8; n++) {
                float4 h = *reinterpret_cast<float4*>(&hid[n * 512 + 4 * h4]);
                acc[n] += w0 * h.x + w1 * h.y + w2 * h.z + w3 * h.w;
            }
        }
        float mx = acc[0];
#pragma unroll
        for (int n = 1; n < 8; n++) mx = fmaxf(mx, acc[n]);
        atomicMaxFloat(out + b * 256 + t, mx + b3b[t]);
    }
}

// ---------------- launch ----------------
extern "C" void kernel_launch(void* const* d_in, const int* in_sizes, int n_in,
                              void* d_out, int out_size) {
    const float* pc  = (const float*)d_in[0];
    const float* W1a = (const float*)d_in[1];
    const float* b1a = (const float*)d_in[2];
    const float* W1b = (const float*)d_in[3];
    const float* b1b = (const float*)d_in[4];
    const float* W2a = (const float*)d_in[5];
    const float* b2a = (const float*)d_in[6];
    const float* W2b = (const float*)d_in[7];
    const float* b2b = (const float*)d_in[8];
    const float* W3a = (const float*)d_in[9];
    const float* b3a = (const float*)d_in[10];
    const float* W3b = (const float*)d_in[11];
    const float* b3b = (const float*)d_in[12];
    float* out = (float*)d_out;

    prep_weights<<<(322560 + 255) / 256, 256>>>(W1a, W1b, W2a, W2b, W3a, W3b);

    // SA1
    fps_kernel<N0, P1, 1024, -1, OFF_FPS1><<<BB, 1024>>>(pc);
    gather_kernel<N0, P1, -1, OFF_FPS1, OFF_L1XYZ><<<BB, 256>>>(pc);
    knn_kernel<P1, N0, 1024, OFF_L1XYZ, -1, OFF_KNN1><<<BB * (P1 / 8), 256>>>(pc);
    sa1_kernel<<<BB * P1, 128>>>(pc, b1a, b1b);

    // SA2
    fps_kernel<P1, P2, 512, OFF_L1XYZ, OFF_FPS2><<<BB, 512>>>(nullptr);
    gather_kernel<P1, P2, OFF_L1XYZ, OFF_FPS2, OFF_L2XYZ><<<BB, 128>>>(nullptr);
    knn_kernel<P2, P1, 512, OFF_L2XYZ, OFF_L1XYZ, OFF_KNN2><<<BB * (P2 / 8), 256>>>(nullptr);
    sa2_kernel<<<BB * P2, 128>>>(b2a, b2b);

    // SA3 (global max into output)
    init_out_kernel<<<16, 256>>>(out, BB * 256);
    sa3_kernel<<<BB * 16, 256>>>(b3a, b3b, out);
}

// round 3
// speedup vs baseline: 1.1028x; 1.1028x over previous
#include <cuda_runtime.h>
#include <cstdint>

typedef unsigned long long ull;

// ---------------- problem constants ----------------
constexpr int BB = 16;
constexpr int N0 = 8192;
constexpr int P1 = 512;
constexpr int P2 = 128;
constexpr int KNN = 16;
constexpr int C1 = 128;   // SA1 out channels
constexpr int C2 = 256;   // SA2 out channels

// ---------------- packed f32x2 helpers ----------------
__device__ __forceinline__ ull pk2(float lo, float hi) {
    ull r; asm("mov.b64 %0, {%1,%2};" : "=l"(r) : "f"(lo), "f"(hi)); return r;
}
__device__ __forceinline__ void upk2(ull v, float& lo, float& hi) {
    asm("mov.b64 {%0,%1}, %2;" : "=f"(lo), "=f"(hi) : "l"(v));
}
__device__ __forceinline__ ull add2(ull a, ull b) {
    ull d; asm("add.rn.f32x2 %0, %1, %2;" : "=l"(d) : "l"(a), "l"(b)); return d;
}
__device__ __forceinline__ ull mul2(ull a, ull b) {
    ull d; asm("mul.rn.f32x2 %0, %1, %2;" : "=l"(d) : "l"(a), "l"(b)); return d;
}
__device__ __forceinline__ ull fma2(ull a, ull b, ull c) {
    ull d; asm("fma.rn.f32x2 %0, %1, %2, %3;" : "=l"(d) : "l"(a), "l"(b), "l"(c)); return d;
}

// ---------------- scratch arena (device globals; no allocation) ----------------
// xyz planar (B,3,P); features point-major (B,P,C).
// Weights stored PAIR-INTERLEAVED: WP[i2][o] = float2(W[o][2*i2], W[o][2*i2+1]),
// float-level index = (i2*O + o)*2. Padded input channels are zero.
constexpr int OFF_L1XYZ = 0;                              // (B,3,P1)
constexpr int OFF_L1PTS = OFF_L1XYZ + BB * 3 * P1;        // (B,P1,C1)
constexpr int OFF_L2XYZ = OFF_L1PTS + BB * P1 * C1;       // (B,3,P2)
constexpr int OFF_L2PTS = OFF_L2XYZ + BB * 3 * P2;        // (B,P2,C2)
constexpr int OFF_W1AT  = OFF_L2PTS + BB * P2 * C2;       // Ipad=8,  O=64
constexpr int OFF_W1BT  = OFF_W1AT + 8 * 64;              // I=64,    O=128
constexpr int OFF_W2AT  = OFF_W1BT + 64 * 128;            // Ipad=132,O=128
constexpr int OFF_W2BT  = OFF_W2AT + 132 * 128;           // I=128,   O=256
constexpr int OFF_W3AT  = OFF_W2BT + 128 * 256;           // Ipad=260,O=512
constexpr int OFF_W3BT  = OFF_W3AT + 260 * 512;           // I=512,   O=256
constexpr int F_TOTAL   = OFF_W3BT + 512 * 256;

constexpr int OFF_FPS1 = 0;
constexpr int OFF_KNN1 = OFF_FPS1 + BB * P1;
constexpr int OFF_FPS2 = OFF_KNN1 + BB * P1 * KNN;
constexpr int OFF_KNN2 = OFF_FPS2 + BB * P2;
constexpr int I_TOTAL  = OFF_KNN2 + BB * P2 * KNN;

__device__ float g_f[F_TOTAL];
__device__ int   g_i[I_TOTAL];

// ---------------- weight prep: W(O,Isrc) -> pair-interleaved WP ----------------
__global__ void prep_weights(const float* __restrict__ W1a, const float* __restrict__ W1b,
                             const float* __restrict__ W2a, const float* __restrict__ W2b,
                             const float* __restrict__ W3a, const float* __restrict__ W3b) {
    int idx = blockIdx.x * blockDim.x + threadIdx.x;
    if (idx < 512) {                      // W1A: O=64, Isrc=6
        int i2 = idx >> 7, rem = idx & 127, o = rem >> 1, h = rem & 1, i = 2 * i2 + h;
        g_f[OFF_W1AT + idx] = (i < 6) ? W1a[o * 6 + i] : 0.f; return;
    }
    idx -= 512;
    if (idx < 8192) {                     // W1B: O=128, Isrc=64
        int i2 = idx >> 8, rem = idx & 255, o = rem >> 1, h = rem & 1, i = 2 * i2 + h;
        g_f[OFF_W1BT + idx] = W1b[o * 64 + i]; return;
    }
    idx -= 8192;
    if (idx < 16896) {                    // W2A: O=128, Isrc=131
        int i2 = idx >> 8, rem = idx & 255, o = rem >> 1, h = rem & 1, i = 2 * i2 + h;
        g_f[OFF_W2AT + idx] = (i < 131) ? W2a[o * 131 + i] : 0.f; return;
    }
    idx -= 16896;
    if (idx < 32768) {                    // W2B: O=256, Isrc=128
        int i2 = idx >> 9, rem = idx & 511, o = rem >> 1, h = rem & 1, i = 2 * i2 + h;
        g_f[OFF_W2BT + idx] = W2b[o * 128 + i]; return;
    }
    idx -= 32768;
    if (idx < 133120) {                   // W3A: O=512, Isrc=259
        int i2 = idx >> 10, rem = idx & 1023, o = rem >> 1, h = rem & 1, i = 2 * i2 + h;
        g_f[OFF_W3AT + idx] = (i < 259) ? W3a[o * 259 + i] : 0.f; return;
    }
    idx -= 133120;
    if (idx < 131072) {                   // W3B: O=256, Isrc=512
        int i2 = idx >> 9, rem = idx & 511, o = rem >> 1, h = rem & 1, i = 2 * i2 + h;
        g_f[OFF_W3BT + idx] = W3b[o * 512 + i]; return;
    }
}

// ---------------- farthest point sampling ----------------
// One block per batch. Packed f32x2 distance update — per-lane arithmetic is
// BIT-IDENTICAL to the verified scalar form (add2(p, -c) == __fsub_rn, .rn
// mul/add chain in the same order, scalar fminf + same argmax scan order).
template <int N, int NPOINT, int THREADS, int XYZ_OFF, int IDX_OFF>
__global__ void __launch_bounds__(THREADS) fps_kernel(const float* __restrict__ xyz_in) {
    static_assert(N % (2 * THREADS) == 0, "packing requires even PPT");
    constexpr int PH = N / THREADS / 2;
    const float* xyz;
    if constexpr (XYZ_OFF >= 0) xyz = g_f + XYZ_OFF; else xyz = xyz_in;

    int b = blockIdx.x, t = threadIdx.x;
    const float* xb = xyz + (size_t)b * 3 * N;

    ull px2[PH], py2[PH], pz2[PH];
    float dd[2 * PH];
#pragma unroll
    for (int k = 0; k < PH; k++) {
        int p0 = t + (2 * k) * THREADS, p1 = t + (2 * k + 1) * THREADS;
        px2[k] = pk2(xb[p0], xb[p1]);
        py2[k] = pk2(xb[N + p0], xb[N + p1]);
        pz2[k] = pk2(xb[2 * N + p0], xb[2 * N + p1]);
        dd[2 * k] = 1e10f; dd[2 * k + 1] = 1e10f;
    }

    __shared__ float sv[THREADS / 32];
    __shared__ int   si[THREADS / 32];
    __shared__ int   sfar;

    int far = 0;
    int* ob = g_i + IDX_OFF + b * NPOINT;

    for (int j = 0; j < NPOINT; j++) {
        if (t == 0) ob[j] = far;
        float cx = __ldg(xb + far);
        float cy = __ldg(xb + N + far);
        float cz = __ldg(xb + 2 * N + far);
        ull ncx2 = pk2(-cx, -cx), ncy2 = pk2(-cy, -cy), ncz2 = pk2(-cz, -cz);

        float best = -1e30f; int bidx = 0x7fffffff;
#pragma unroll
        for (int k = 0; k < PH; k++) {
            ull dx2 = add2(px2[k], ncx2);
            ull dy2 = add2(py2[k], ncy2);
            ull dz2 = add2(pz2[k], ncz2);
            ull s2 = add2(add2(mul2(dx2, dx2), mul2(dy2, dy2)), mul2(dz2, dz2));
            float d0, d1; upk2(s2, d0, d1);
            float nd0 = fminf(dd[2 * k], d0);     dd[2 * k] = nd0;
            if (nd0 > best) { best = nd0; bidx = t + (2 * k) * THREADS; }
            float nd1 = fminf(dd[2 * k + 1], d1); dd[2 * k + 1] = nd1;
            if (nd1 > best) { best = nd1; bidx = t + (2 * k + 1) * THREADS; }
        }
#pragma unroll
        for (int off = 16; off; off >>= 1) {
            float ov = __shfl_down_sync(0xffffffffu, best, off);
            int   oi = __shfl_down_sync(0xffffffffu, bidx, off);
            if (ov > best || (ov == best && oi < bidx)) { best = ov; bidx = oi; }
        }
        if ((t & 31) == 0) { sv[t >> 5] = best; si[t >> 5] = bidx; }
        __syncthreads();
        if (t < 32) {
            constexpr int NW = THREADS / 32;
            float v = (t < NW) ? sv[t] : -1e30f;
            int  ix = (t < NW) ? si[t] : 0x7fffffff;
#pragma unroll
            for (int off = 16; off; off >>= 1) {
                float ov = __shfl_down_sync(0xffffffffu, v, off);
                int   oi = __shfl_down_sync(0xffffffffu, ix, off);
                if (ov > v || (ov == v && oi < ix)) { v = ov; ix = oi; }
            }
            if (t == 0) sfar = ix;
        }
        __syncthreads();
        far = sfar;
    }
}

// ---------------- gather sampled xyz (planar -> planar) ----------------
template <int NSRC, int PDST, int SRC_OFF, int IDX_OFF, int DST_OFF>
__global__ void gather_kernel(const float* __restrict__ src_in) {
    const float* src;
    if constexpr (SRC_OFF >= 0) src = g_f + SRC_OFF; else src = src_in;
    int b = blockIdx.x;
    for (int p = threadIdx.x; p < PDST; p += blockDim.x) {
        int j = g_i[IDX_OFF + b * PDST + p];
#pragma unroll
        for (int c = 0; c < 3; c++)
            g_f[DST_OFF + (b * 3 + c) * PDST + p] = src[((size_t)b * 3 + c) * NSRC + j];
    }
}

// ---------------- kNN (UNCHANGED from verified R2 version) ----------------
__device__ __forceinline__ ull pack_key(float d, int i) {
    unsigned b = __float_as_uint(d);
    b = (b & 0x80000000u) ? ~b : (b | 0x80000000u);
    return ((ull)b << 32) | (unsigned)i;
}

template <int P, int N, int TILE, int CENT_OFF, int PTS_OFF, int OUT_OFF>
__global__ void __launch_bounds__(256) knn_kernel(const float* __restrict__ pts_in) {
    __shared__ float sx[TILE], sy[TILE], sz[TILE];
    const float* cent = g_f + CENT_OFF;
    const float* pts;
    if constexpr (PTS_OFF >= 0) pts = g_f + PTS_OFF; else pts = pts_in;

    int b = blockIdx.x / (P / 8);
    int p = (blockIdx.x % (P / 8)) * 8 + (threadIdx.x >> 5);
    int lane = threadIdx.x & 31;

    const float* cb = cent + b * 3 * P;
    const float* pb = pts + (size_t)b * 3 * N;
    float cx = cb[p], cy = cb[P + p], cz = cb[2 * P + p];
    float c2 = cx * cx + cy * cy + cz * cz;

    ull mykey = 0xFF800000FFFFFFFFull;
    float thrf = __int_as_float(0x7f800000);

    for (int t0 = 0; t0 < N; t0 += TILE) {
        __syncthreads();
        for (int i = threadIdx.x; i < TILE; i += 256) {
            sx[i] = pb[t0 + i];
            sy[i] = pb[N + t0 + i];
            sz[i] = pb[2 * N + t0 + i];
        }
        __syncthreads();
        for (int c0 = 0; c0 < TILE; c0 += 32) {
            int ii = c0 + lane;
            float x = sx[ii], y = sy[ii], z = sz[ii];
            float d = c2 - 2.f * (cx * x + cy * y + cz * z) + (x * x + y * y + z * z);
            unsigned m = __ballot_sync(0xffffffffu, d <= thrf);
            if (m) {
                ull key = pack_key(d, t0 + ii);
                while (m) {
                    int src = __ffs(m) - 1;
                    m &= m - 1;
                    ull K = __shfl_sync(0xffffffffu, key, src);
                    ull thr = __shfl_sync(0xffffffffu, mykey, 15);
                    ull up = __shfl_up_sync(0xffffffffu, mykey, 1);
                    if (K < thr && lane < 16 && mykey > K)
                        mykey = (lane > 0 && up > K) ? up : K;
                }
                ull k15 = __shfl_sync(0xffffffffu, mykey, 15);
                unsigned hb = (unsigned)(k15 >> 32);
                unsigned obits = (hb & 0x80000000u) ? (hb & 0x7fffffffu) : ~hb;
                thrf = __uint_as_float(obits);
            }
        }
    }
    if (lane < 16)
        g_i[OUT_OFF + ((b * P + p) << 4) + lane] = (int)(mykey & 0xffffffffu);
}

// ---------------- SA1: group + MLP(6->64 relu ->128) + maxpool (FFMA2) ----------------
__global__ void __launch_bounds__(128) sa1_kernel(const float* __restrict__ xyz,
                                                  const float* __restrict__ b1a,
                                                  const float* __restrict__ b1b) {
    __shared__ alignas(16) float feat[16 * 8];
    __shared__ alignas(16) float hid[16 * 64];
    int t = threadIdx.x;
    int cid = blockIdx.x;
    int b = cid >> 9, p = cid & 511;

    if (t < 16) {
        int j = g_i[OFF_KNN1 + (cid << 4) + t];
        const float* xb = xyz + (size_t)b * 3 * N0;
        float vx = xb[j], vy = xb[N0 + j], vz = xb[2 * N0 + j];
        const float* cxb = g_f + OFF_L1XYZ + b * 3 * P1;
        feat[t * 8 + 0] = vx - cxb[p];
        feat[t * 8 + 1] = vy - cxb[P1 + p];
        feat[t * 8 + 2] = vz - cxb[2 * P1 + p];
        feat[t * 8 + 3] = vx;
        feat[t * 8 + 4] = vy;
        feat[t * 8 + 5] = vz;
        feat[t * 8 + 6] = 0.f;
        feat[t * 8 + 7] = 0.f;
    }
    __syncthreads();

    if (t < 64) {
        ull acc[16];
#pragma unroll
        for (int n = 0; n < 16; n++) acc[n] = 0ull;
#pragma unroll
        for (int i4 = 0; i4 < 2; i4++) {
            ull wA = *(const ull*)&g_f[OFF_W1AT + ((2 * i4) * 64 + t) * 2];
            ull wB = *(const ull*)&g_f[OFF_W1AT + ((2 * i4 + 1) * 64 + t) * 2];
#pragma unroll
            for (int n = 0; n < 16; n++) {
                ulonglong2 f = *(const ulonglong2*)&feat[n * 8 + 4 * i4];
                acc[n] = fma2(wA, f.x, acc[n]);
                acc[n] = fma2(wB, f.y, acc[n]);
            }
        }
        float bb = b1a[t];
#pragma unroll
        for (int n = 0; n < 16; n++) {
            float e, o; upk2(acc[n], e, o);
            hid[n * 64 + t] = fmaxf(e + o + bb, 0.f);
        }
    }
    __syncthreads();

    {
        ull acc[16];
#pragma unroll
        for (int n = 0; n < 16; n++) acc[n] = 0ull;
#pragma unroll 4
        for (int h4 = 0; h4 < 16; h4++) {
            ull wA = *(const ull*)&g_f[OFF_W1BT + ((2 * h4) * 128 + t) * 2];
            ull wB = *(const ull*)&g_f[OFF_W1BT + ((2 * h4 + 1) * 128 + t) * 2];
#pragma unroll
            for (int n = 0; n < 16; n++) {
                ulonglong2 f = *(const ulonglong2*)&hid[n * 64 + 4 * h4];
                acc[n] = fma2(wA, f.x, acc[n]);
                acc[n] = fma2(wB, f.y, acc[n]);
            }
        }
        float mx = -1e30f;
#pragma unroll
        for (int n = 0; n < 16; n++) {
            float e, o; upk2(acc[n], e, o);
            mx = fmaxf(mx, e + o);
        }
        g_f[OFF_L1PTS + ((size_t)(b * P1 + p)) * C1 + t] = mx + b1b[t];
    }
}

// ---------------- SA2: group + MLP(131->128 relu ->256) + maxpool (FFMA2) ----------------
__global__ void __launch_bounds__(128) sa2_kernel(const float* __restrict__ b2a,
                                                  const float* __restrict__ b2b) {
    __shared__ alignas(16) float feat[16 * 132];
    __shared__ alignas(16) float hid[16 * 128];
    __shared__ int sj[16];
    int t = threadIdx.x;
    int cid = blockIdx.x;
    int b = cid >> 7, p = cid & 127;

    if (t < 16) sj[t] = g_i[OFF_KNN2 + (cid << 4) + t];
    __syncthreads();

    for (int idx = t; idx < 16 * 132; idx += 128) {
        int n = idx / 132, c = idx - n * 132;
        int j = sj[n];
        float v;
        if (c < 3)
            v = g_f[OFF_L1XYZ + (b * 3 + c) * P1 + j] - g_f[OFF_L2XYZ + (b * 3 + c) * P2 + p];
        else if (c < 131)
            v = g_f[OFF_L1PTS + ((size_t)(b * P1 + j)) * C1 + (c - 3)];
        else
            v = 0.f;
        feat[idx] = v;
    }
    __syncthreads();

    {
        ull acc[16];
#pragma unroll
        for (int n = 0; n < 16; n++) acc[n] = 0ull;
#pragma unroll 3
        for (int i4 = 0; i4 < 33; i4++) {
            ull wA = *(const ull*)&g_f[OFF_W2AT + ((2 * i4) * 128 + t) * 2];
            ull wB = *(const ull*)&g_f[OFF_W2AT + ((2 * i4 + 1) * 128 + t) * 2];
#pragma unroll
            for (int n = 0; n < 16; n++) {
                ulonglong2 f = *(const ulonglong2*)&feat[n * 132 + 4 * i4];
                acc[n] = fma2(wA, f.x, acc[n]);
                acc[n] = fma2(wB, f.y, acc[n]);
            }
        }
        float bb = b2a[t];
#pragma unroll
        for (int n = 0; n < 16; n++) {
            float e, o; upk2(acc[n], e, o);
            hid[n * 128 + t] = fmaxf(e + o + bb, 0.f);
        }
    }
    __syncthreads();

#pragma unroll
    for (int cc = 0; cc < 2; cc++) {
        int o = t + cc * 128;
        ull acc[16];
#pragma unroll
        for (int n = 0; n < 16; n++) acc[n] = 0ull;
#pragma unroll 4
        for (int h4 = 0; h4 < 32; h4++) {
            ull wA = *(const ull*)&g_f[OFF_W2BT + ((2 * h4) * 256 + o) * 2];
            ull wB = *(const ull*)&g_f[OFF_W2BT + ((2 * h4 + 1) * 256 + o) * 2];
#pragma unroll
            for (int n = 0; n < 16; n++) {
                ulonglong2 f = *(const ulonglong2*)&hid[n * 128 + 4 * h4];
                acc[n] = fma2(wA, f.x, acc[n]);
                acc[n] = fma2(wB, f.y, acc[n]);
            }
        }
        float mx = -1e30f;
#pragma unroll
        for (int n = 0; n < 16; n++) {
            float e, oo; upk2(acc[n], e, oo);
            mx = fmaxf(mx, e + oo);
        }
        g_f[OFF_L2PTS + ((size_t)(b * P2 + p)) * C2 + o] = mx + b2b[o];
    }
}

// ---------------- SA3: group-all MLP(259->512 relu ->256) + global max ----------------
__device__ __forceinline__ void atomicMaxFloat(float* addr, float v) {
    if (v >= 0.f) atomicMax((int*)addr, __float_as_int(v));
    else          atomicMin((unsigned*)addr, __float_as_uint(v));
}

__global__ void init_out_kernel(float* out, int n) {
    int i = blockIdx.x * blockDim.x + threadIdx.x;
    if (i < n) out[i] = __int_as_float(0xff800000);
}

__global__ void __launch_bounds__(256) sa3_kernel(const float* __restrict__ b3a,
                                                  const float* __restrict__ b3b,
                                                  float* __restrict__ out) {
    __shared__ alignas(16) float feat[8 * 260];
    __shared__ alignas(16) float hid[8 * 512];
    int t = threadIdx.x;
    int b = blockIdx.x >> 4, tile = blockIdx.x & 15;

    for (int idx = t; idx < 8 * 260; idx += 256) {
        int n = idx / 260, c = idx - n * 260;
        int pt = tile * 8 + n;
        float v;
        if (c < 3)        v = g_f[OFF_L2XYZ + (b * 3 + c) * P2 + pt];
        else if (c < 259) v = g_f[OFF_L2PTS + ((size_t)(b * P2 + pt)) * C2 + (c - 3)];
        else              v = 0.f;
        feat[idx] = v;
    }
    __syncthreads();

#pragma unroll
    for (int cc = 0; cc < 2; cc++) {
        int h = t + cc * 256;
        ull acc[8];
#pragma unroll
        for (int n = 0; n < 8; n++) acc[n] = 0ull;
#pragma unroll 5
        for (int i4 = 0; i4 < 65; i4++) {
            ull wA = *(const ull*)&g_f[OFF_W3AT + ((2 * i4) * 512 + h) * 2];
            ull wB = *(const ull*)&g_f[OFF_W3AT + ((2 * i4 + 1) * 512 + h) * 2];
#pragma unroll
            for (int n = 0; n < 8; n++) {
                ulonglong2 f = *(const ulonglong2*)&feat[n * 260 + 4 * i4];
                acc[n] = fma2(wA, f.x, acc[n]);
                acc[n] = fma2(wB, f.y, acc[n]);
            }
        }
        float bb = b3a[h];
#pragma unroll
        for (int n = 0; n < 8; n++) {
            float e, o; upk2(acc[n], e, o);
            hid[n * 512 + h] = fmaxf(e + o + bb, 0.f);
        }
    }
    __syncthreads();

    {
        ull acc[8];
#pragma unroll
        for (int n = 0; n < 8; n++) acc[n] = 0ull;
#pragma unroll 4
        for (int h4 = 0; h4 < 128; h4++) {
            ull wA = *(const ull*)&g_f[OFF_W3BT + ((2 * h4) * 256 + t) * 2];
            ull wB = *(const ull*)&g_f[OFF_W3BT + ((2 * h4 + 1) * 256 + t) * 2];
#pragma unroll
            for (int n = 0; n < 8; n++) {
                ulonglong2 f = *(const ulonglong2*)&hid[n * 512 + 4 * h4];
                acc[n] = fma2(wA, f.x, acc[n]);
                acc[n] = fma2(wB, f.y, acc[n]);
            }
        }
        float mx = -1e30f;
#pragma unroll
        for (int n = 0; n < 8; n++) {
            float e, o; upk2(acc[n], e, o);
            mx = fmaxf(mx, e + o);
        }
        atomicMaxFloat(out + b * 256 + t, mx + b3b[t]);
    }
}

// ---------------- launch ----------------
extern "C" void kernel_launch(void* const* d_in, const int* in_sizes, int n_in,
                              void* d_out, int out_size) {
    const float* pc  = (const float*)d_in[0];
    const float* W1a = (const float*)d_in[1];
    const float* b1a = (const float*)d_in[2];
    const float* W1b = (const float*)d_in[3];
    const float* b1b = (const float*)d_in[4];
    const float* W2a = (const float*)d_in[5];
    const float* b2a = (const float*)d_in[6];
    const float* W2b = (const float*)d_in[7];
    const float* b2b = (const float*)d_in[8];
    const float* W3a = (const float*)d_in[9];
    const float* b3a = (const float*)d_in[10];
    const float* W3b = (const float*)d_in[11];
    const float* b3b = (const float*)d_in[12];
    float* out = (float*)d_out;

    prep_weights<<<(322560 + 255) / 256, 256>>>(W1a, W1b, W2a, W2b, W3a, W3b);

    // SA1
    fps_kernel<N0, P1, 1024, -1, OFF_FPS1><<<BB, 1024>>>(pc);
    gather_kernel<N0, P1, -1, OFF_FPS1, OFF_L1XYZ><<<BB, 256>>>(pc);
    knn_kernel<P1, N0, 1024, OFF_L1XYZ, -1, OFF_KNN1><<<BB * (P1 / 8), 256>>>(pc);
    sa1_kernel<<<BB * P1, 128>>>(pc, b1a, b1b);

    // SA2
    fps_kernel<P1, P2, 256, OFF_L1XYZ, OFF_FPS2><<<BB, 256>>>(nullptr);
    gather_kernel<P1, P2, OFF_L1XYZ, OFF_FPS2, OFF_L2XYZ><<<BB, 128>>>(nullptr);
    knn_kernel<P2, P1, 512, OFF_L2XYZ, OFF_L1XYZ, OFF_KNN2><<<BB * (P2 / 8), 256>>>(nullptr);
    sa2_kernel<<<BB * P2, 128>>>(b2a, b2b);

    // SA3 (global max into output)
    init_out_kernel<<<16, 256>>>(out, BB * 256);
    sa3_kernel<<<BB * 16, 256>>>(b3a, b3b, out);
}